// round 1
// baseline (speedup 1.0000x reference)
#include <cuda_runtime.h>

#define BB 8
#define NN 5000
#define EE 100000
#define DD 128

// Scratch (allocation-free: __device__ globals)
__device__ float g_sums[BB * NN * DD];   // segment sums, [B*N, 128]
__device__ float g_cnt[BB * NN];         // segment counts (sum of edge_mask)

// ---------------------------------------------------------------------------
// Kernel 1: zero the scratch accumulators
// ---------------------------------------------------------------------------
__global__ void zero_kernel() {
    const size_t total4 = (size_t)BB * NN * DD / 4;
    float4 z = make_float4(0.f, 0.f, 0.f, 0.f);
    float4* s4 = (float4*)g_sums;
    size_t stride = (size_t)gridDim.x * blockDim.x;
    for (size_t i = (size_t)blockIdx.x * blockDim.x + threadIdx.x; i < total4; i += stride)
        s4[i] = z;
    for (size_t i = (size_t)blockIdx.x * blockDim.x + threadIdx.x; i < (size_t)BB * NN; i += stride)
        g_cnt[i] = 0.f;
}

// ---------------------------------------------------------------------------
// Kernel 2: edge scatter. One warp per edge. Each lane handles one float4
// (32 lanes x 16B = 512B row). Vector reduction red.global.add.v4.f32.
// ---------------------------------------------------------------------------
__global__ void scatter_kernel(const float* __restrict__ x,
                               const int* __restrict__ ei,
                               const float* __restrict__ em) {
    int gw = (blockIdx.x * blockDim.x + threadIdx.x) >> 5;
    int lane = threadIdx.x & 31;
    if (gw >= BB * EE) return;
    int b = gw / EE;
    int e = gw - b * EE;
    const int* eb = ei + (size_t)b * 2 * EE;
    int src = __ldg(&eb[e]);
    int tgt = __ldg(&eb[EE + e]);
    float m = __ldg(&em[(size_t)b * EE + e]);
    if (m == 0.f) return;  // contributes 0 to both sums and cnt

    const float4* srow = (const float4*)(x + ((size_t)b * NN + src) * DD);
    float4 v = srow[lane];
    float* dst = g_sums + ((size_t)b * NN + tgt) * DD + lane * 4;
    asm volatile("red.global.add.v4.f32 [%0], {%1, %2, %3, %4};"
                 :: "l"(dst), "f"(v.x * m), "f"(v.y * m), "f"(v.z * m), "f"(v.w * m)
                 : "memory");
    if (lane == 0)
        atomicAdd(g_cnt + (size_t)b * NN + tgt, m);
}

// ---------------------------------------------------------------------------
// Kernel 3: fused  out = LN(relu(x@Wself + (sums/max(cnt,1))@Wnb + b)) * mask
//
// Persistent blocks. Each block: loads concatenated weight Wc [256][128]
// (rows 0..127 = W_self, 128..255 = W_nb) into shared once, then loops over
// tiles of 64 nodes. Shared input tile inS [64 nodes][256 k] holds x || agg.
//
// Thread layout (512 threads = 16 warps): cg = tid&31 (column quad, cols
// 4cg..4cg+3), ng = tid>>5 (warp -> 4 nodes). Each thread: 4 cols x 4 nodes
// = 16 fp32 accumulators. Warp owns 4 full node rows -> layernorm via
// warp shuffle reduce.
// ---------------------------------------------------------------------------
#define TILE_NODES 64
#define FUSED_THREADS 512
#define SMEM_W4 (256 * 32)           // Wc: 256 rows x 32 float4
#define SMEM_IN4 (TILE_NODES * 64)   // inS: 64 nodes x 64 float4 (256 floats)
#define FUSED_SMEM_BYTES ((SMEM_W4 + SMEM_IN4) * 16)

__global__ void __launch_bounds__(FUSED_THREADS, 1)
fused_kernel(const float* __restrict__ x,
             const float* __restrict__ Wself,
             const float* __restrict__ bself,
             const float* __restrict__ Wnb,
             const float* __restrict__ bnb,
             const float* __restrict__ gamma,
             const float* __restrict__ beta,
             const float* __restrict__ nmask,
             float* __restrict__ out) {
    extern __shared__ float4 smem[];
    float4* Wc = smem;                 // [256][32] float4
    float4* inS = smem + SMEM_W4;      // [64][64] float4

    const int tid = threadIdx.x;
    const int cg = tid & 31;   // column group (4 cols)
    const int ng = tid >> 5;   // warp id -> node group (4 nodes)

    // Load concatenated weights into shared (once per block)
    const float4* Ws4 = (const float4*)Wself;
    const float4* Wn4 = (const float4*)Wnb;
    for (int i = tid; i < SMEM_W4; i += FUSED_THREADS) {
        int k = i >> 5;
        int c = i & 31;
        Wc[i] = (k < 128) ? Ws4[k * 32 + c] : Wn4[(k - 128) * 32 + c];
    }
    __syncthreads();

    // Constants per thread (cols 4cg..4cg+3)
    float4 bs = ((const float4*)bself)[cg];
    float4 bn = ((const float4*)bnb)[cg];
    const float bias_x = bs.x + bn.x, bias_y = bs.y + bn.y;
    const float bias_z = bs.z + bn.z, bias_w = bs.w + bn.w;
    const float4 gm = ((const float4*)gamma)[cg];
    const float4 bt = ((const float4*)beta)[cg];

    const int ntiles = (BB * NN) / TILE_NODES;  // 625
    const float4* x4 = (const float4*)x;
    const float4* s4 = (const float4*)g_sums;

    for (int tile = blockIdx.x; tile < ntiles; tile += gridDim.x) {
        const int node0 = tile * TILE_NODES;

        // Load input tile: inS[nl][k4] : k4<32 -> x row, k4>=32 -> agg row
        for (int i = tid; i < SMEM_IN4; i += FUSED_THREADS) {
            int nl = i >> 6;
            int k4 = i & 63;
            int gn = node0 + nl;
            float4 v;
            if (k4 < 32) {
                v = x4[(size_t)gn * 32 + k4];
            } else {
                float c = g_cnt[gn];
                float inv = 1.f / fmaxf(c, 1.f);
                float4 s = s4[(size_t)gn * 32 + (k4 - 32)];
                v = make_float4(s.x * inv, s.y * inv, s.z * inv, s.w * inv);
            }
            inS[i] = v;
        }
        __syncthreads();

        float4 acc0 = make_float4(bias_x, bias_y, bias_z, bias_w);
        float4 acc1 = acc0, acc2 = acc0, acc3 = acc0;

        const float4* in0 = inS + (ng * 4 + 0) * 64;
        const float4* in1 = inS + (ng * 4 + 1) * 64;
        const float4* in2 = inS + (ng * 4 + 2) * 64;
        const float4* in3 = inS + (ng * 4 + 3) * 64;

#define KSTEP(J, COMP)                                                        \
        {                                                                     \
            float4 w = Wc[(k4 * 4 + J) * 32 + cg];                            \
            acc0.x = fmaf(a0.COMP, w.x, acc0.x);                              \
            acc0.y = fmaf(a0.COMP, w.y, acc0.y);                              \
            acc0.z = fmaf(a0.COMP, w.z, acc0.z);                              \
            acc0.w = fmaf(a0.COMP, w.w, acc0.w);                              \
            acc1.x = fmaf(a1.COMP, w.x, acc1.x);                              \
            acc1.y = fmaf(a1.COMP, w.y, acc1.y);                              \
            acc1.z = fmaf(a1.COMP, w.z, acc1.z);                              \
            acc1.w = fmaf(a1.COMP, w.w, acc1.w);                              \
            acc2.x = fmaf(a2.COMP, w.x, acc2.x);                              \
            acc2.y = fmaf(a2.COMP, w.y, acc2.y);                              \
            acc2.z = fmaf(a2.COMP, w.z, acc2.z);                              \
            acc2.w = fmaf(a2.COMP, w.w, acc2.w);                              \
            acc3.x = fmaf(a3.COMP, w.x, acc3.x);                              \
            acc3.y = fmaf(a3.COMP, w.y, acc3.y);                              \
            acc3.z = fmaf(a3.COMP, w.z, acc3.z);                              \
            acc3.w = fmaf(a3.COMP, w.w, acc3.w);                              \
        }

#pragma unroll 4
        for (int k4 = 0; k4 < 64; ++k4) {
            float4 a0 = in0[k4];
            float4 a1 = in1[k4];
            float4 a2 = in2[k4];
            float4 a3 = in3[k4];
            KSTEP(0, x)
            KSTEP(1, y)
            KSTEP(2, z)
            KSTEP(3, w)
        }
#undef KSTEP

        // Epilogue: relu + layernorm (warp owns 4 node rows) + affine + mask
        float4 accs[4] = {acc0, acc1, acc2, acc3};
#pragma unroll
        for (int n = 0; n < 4; ++n) {
            float4 h = accs[n];
            h.x = fmaxf(h.x, 0.f);
            h.y = fmaxf(h.y, 0.f);
            h.z = fmaxf(h.z, 0.f);
            h.w = fmaxf(h.w, 0.f);
            float part = h.x + h.y + h.z + h.w;
#pragma unroll
            for (int o = 16; o > 0; o >>= 1)
                part += __shfl_xor_sync(0xFFFFFFFFu, part, o);
            float mu = part * (1.f / 128.f);
            float dx = h.x - mu, dy = h.y - mu, dz = h.z - mu, dw = h.w - mu;
            float p2 = dx * dx + dy * dy + dz * dz + dw * dw;
#pragma unroll
            for (int o = 16; o > 0; o >>= 1)
                p2 += __shfl_xor_sync(0xFFFFFFFFu, p2, o);
            float rstd = rsqrtf(p2 * (1.f / 128.f) + 1e-5f);

            int gn = node0 + ng * 4 + n;
            float mask = __ldg(&nmask[gn]);
            float4 o4;
            o4.x = (dx * rstd * gm.x + bt.x) * mask;
            o4.y = (dy * rstd * gm.y + bt.y) * mask;
            o4.z = (dz * rstd * gm.z + bt.z) * mask;
            o4.w = (dw * rstd * gm.w + bt.w) * mask;
            ((float4*)out)[(size_t)gn * 32 + cg] = o4;
        }
        __syncthreads();  // protect inS before next tile's load
    }
}

// ---------------------------------------------------------------------------
extern "C" void kernel_launch(void* const* d_in, const int* in_sizes, int n_in,
                              void* d_out, int out_size) {
    const float* x     = (const float*)d_in[0];
    const int*   ei    = (const int*)d_in[1];
    const float* nmask = (const float*)d_in[2];
    const float* emask = (const float*)d_in[3];
    const float* Wself = (const float*)d_in[4];
    const float* bself = (const float*)d_in[5];
    const float* Wnb   = (const float*)d_in[6];
    const float* bnb   = (const float*)d_in[7];
    const float* gamma = (const float*)d_in[8];
    const float* beta  = (const float*)d_in[9];
    float* out = (float*)d_out;

    (void)in_sizes; (void)n_in; (void)out_size;

    zero_kernel<<<1024, 256>>>();

    // One warp per edge: B*E = 800000 warps, 8 warps/block -> 100000 blocks
    scatter_kernel<<<(BB * EE * 32) / 256, 256>>>(x, ei, emask);

    cudaFuncSetAttribute(fused_kernel, cudaFuncAttributeMaxDynamicSharedMemorySize,
                         FUSED_SMEM_BYTES);
    int nsm = 148;
    cudaDeviceGetAttribute(&nsm, cudaDevAttrMultiProcessorCount, 0);
    fused_kernel<<<nsm, FUSED_THREADS, FUSED_SMEM_BYTES>>>(
        x, Wself, bself, Wnb, bnb, gamma, beta, nmask, out);
}